// round 13
// baseline (speedup 1.0000x reference)
#include <cuda_runtime.h>
#include <cuda_fp16.h>
#include <cstdint>

#define B_   2
#define S_   2048
#define D_   1024
#define H_   16
#define DK_  64
#define DFF_ 4096
#define ROWS (B_*S_)     // 4096
#define QKV_S (3*D_)     // 3072

// ---------------- scratch (device globals; no allocations allowed) ----------
__device__ __half g_nxh [ROWS*D_];      // LN1 out
__device__ __half g_qkvh[ROWS*QKV_S];   // packed q|k|v
__device__ __half g_ctxh[ROWS*D_];      // attention context
__device__ float  g_x1  [ROWS*D_];      // x after attn residual (fp32)
__device__ __half g_nx2h[ROWS*D_];      // LN2 out
__device__ __half g_hh  [ROWS*DFF_];    // ffn hidden
// fp16 weights
__device__ __half g_wqkvh[3*D_*D_];
__device__ float  g_bqkv[3*D_];
__device__ __half g_woh[D_*D_];
__device__ __half g_w1h[DFF_*D_], g_w2h[D_*DFF_];

// ---------------- helpers ----------------------------------------------------
__device__ __forceinline__ uint32_t smem_u32(const void* p) {
    uint32_t a;
    asm("{ .reg .u64 t; cvta.to.shared.u64 t, %1; cvt.u32.u64 %0, t; }"
        : "=r"(a) : "l"(p));
    return a;
}
__device__ __forceinline__ void cp16(uint32_t dst, const void* src) {
    asm volatile("cp.async.cg.shared.global [%0], [%1], 16;"
                 :: "r"(dst), "l"(src) : "memory");
}
__device__ __forceinline__ void cp_commit() {
    asm volatile("cp.async.commit_group;" ::: "memory");
}
__device__ __forceinline__ void ldsm4(uint32_t* r, uint32_t addr) {
    asm volatile("ldmatrix.sync.aligned.m8n8.x4.shared.b16 {%0,%1,%2,%3}, [%4];"
                 : "=r"(r[0]), "=r"(r[1]), "=r"(r[2]), "=r"(r[3]) : "r"(addr));
}
__device__ __forceinline__ void ldsm4t(uint32_t* r, uint32_t addr) {
    asm volatile("ldmatrix.sync.aligned.m8n8.x4.trans.shared.b16 {%0,%1,%2,%3}, [%4];"
                 : "=r"(r[0]), "=r"(r[1]), "=r"(r[2]), "=r"(r[3]) : "r"(addr));
}
// m16n8k16 fp16, fp32 accumulate
__device__ __forceinline__ void mma16h(float* c, const uint32_t* a,
                                       uint32_t b0, uint32_t b1) {
    asm volatile(
        "mma.sync.aligned.m16n8k16.row.col.f32.f16.f16.f32 "
        "{%0,%1,%2,%3}, {%4,%5,%6,%7}, {%8,%9}, {%0,%1,%2,%3};"
        : "+f"(c[0]), "+f"(c[1]), "+f"(c[2]), "+f"(c[3])
        : "r"(a[0]), "r"(a[1]), "r"(a[2]), "r"(a[3]), "r"(b0), "r"(b1));
}
// pack two f32 -> f16x2 (lo = first arg)
__device__ __forceinline__ uint32_t f16pk(float lo, float hi) {
    uint32_t r;
    asm("cvt.rn.f16x2.f32 %0, %1, %2;" : "=r"(r) : "f"(hi), "f"(lo));
    return r;
}

// ---------------- fused weight conversion + bias pack (MLP=4) ----------------
#define NDD4 (D_*D_/4)
#define NDF4 (DFF_*D_/4)
#define CVT_F4   (4*NDD4 + 2*NDF4)
#define BIAS_F4  (3*D_/4)
#define CVT_UNITS (CVT_F4 + BIAS_F4)
#define CVT_GRID ((CVT_UNITS + 1023) / 1024)

__global__ __launch_bounds__(256) void cvt_all_kernel(
    const float* __restrict__ Wq, const float* __restrict__ Wk,
    const float* __restrict__ Wv, const float* __restrict__ Wo,
    const float* __restrict__ W1, const float* __restrict__ W2,
    const float* __restrict__ bq, const float* __restrict__ bk,
    const float* __restrict__ bv,
    __half* __restrict__ wqkv, __half* __restrict__ wo,
    __half* __restrict__ w1h, __half* __restrict__ w2h,
    float* __restrict__ bqkv)
{
    const int base = (blockIdx.x * 256 + threadIdx.x) * 4;
    #pragma unroll
    for (int p = 0; p < 4; p++) {
        const int i = base + p;
        if (i >= CVT_UNITS) break;
        if (i < CVT_F4) {
            const float4* src; __half* dst; int si, off;
            if (i < NDD4)             { src = (const float4*)Wq; si = i;               dst = wqkv; off = i; }
            else if (i < 2*NDD4)      { src = (const float4*)Wk; si = i - NDD4;        dst = wqkv; off = i; }
            else if (i < 3*NDD4)      { src = (const float4*)Wv; si = i - 2*NDD4;      dst = wqkv; off = i; }
            else if (i < 4*NDD4)      { src = (const float4*)Wo; si = i - 3*NDD4;      dst = wo;   off = si; }
            else if (i < 4*NDD4+NDF4) { src = (const float4*)W1; si = i - 4*NDD4;      dst = w1h;  off = si; }
            else                      { src = (const float4*)W2; si = i - 4*NDD4-NDF4; dst = w2h;  off = si; }
            float4 v = src[si];
            uint2 o;
            o.x = f16pk(v.x, v.y);
            o.y = f16pk(v.z, v.w);
            *(uint2*)&dst[(size_t)off * 4] = o;
        } else {
            const int j = i - CVT_F4;
            const float4* s; int sj;
            if (j < 256)      { s = (const float4*)bq; sj = j; }
            else if (j < 512) { s = (const float4*)bk; sj = j - 256; }
            else              { s = (const float4*)bv; sj = j - 512; }
            ((float4*)bqkv)[j] = s[sj];
        }
    }
}

// ---------------- LayerNorm (fp16 out) ----------------------------------------
__global__ __launch_bounds__(256) void ln_kernel(
    const float* __restrict__ x, const float* __restrict__ g,
    const float* __restrict__ bta, __half* __restrict__ out)
{
    const int row = blockIdx.x;
    const int t   = threadIdx.x;
    const float4* xr = (const float4*)(x + (size_t)row * D_);
    float4 v = xr[t];
    float s  = v.x + v.y + v.z + v.w;
    float s2 = v.x*v.x + v.y*v.y + v.z*v.z + v.w*v.w;
    #pragma unroll
    for (int o = 16; o > 0; o >>= 1) {
        s  += __shfl_xor_sync(0xffffffffu, s,  o);
        s2 += __shfl_xor_sync(0xffffffffu, s2, o);
    }
    __shared__ float rs[8], rs2[8];
    const int w = t >> 5;
    if ((t & 31) == 0) { rs[w] = s; rs2[w] = s2; }
    __syncthreads();
    s = 0.f; s2 = 0.f;
    #pragma unroll
    for (int i = 0; i < 8; i++) { s += rs[i]; s2 += rs2[i]; }
    const float mu   = s * (1.0f / D_);
    const float var  = s2 * (1.0f / D_) - mu * mu;
    const float rstd = rsqrtf(var + 1e-5f);
    float4 gg = ((const float4*)g)[t];
    float4 bb = ((const float4*)bta)[t];
    uint2 o;
    o.x = f16pk((v.x - mu) * rstd * gg.x + bb.x,
                (v.y - mu) * rstd * gg.y + bb.y);
    o.y = f16pk((v.z - mu) * rstd * gg.z + bb.z,
                (v.w - mu) * rstd * gg.w + bb.w);
    *(uint2*)(out + (size_t)row * D_ + t * 4) = o;
}

// ---------------- FP16 GEMM-NT: 4 warps, warp tile 64x64, K-tile 64 ----------
enum { EPI_H16 = 0, EPI_RES = 1, EPI_G16 = 2 };
#define STAGES 3
#define STAGE_BYTES 32768
#define GEMM_SMEM (STAGES * STAGE_BYTES)   // 96 KB

template <int EPI>
__global__ __launch_bounds__(128, 2) void gemm_f16(
    int M, int N, int K,
    const __half* __restrict__ A, const __half* __restrict__ Bw,
    const float* __restrict__ bias, const float* __restrict__ resid,
    void* __restrict__ Cout)
{
    extern __shared__ float sm[];
    const int tid  = threadIdx.x;
    const int lane = tid & 31;
    const int wid  = tid >> 5;
    const int wm = wid & 1;
    const int wn = wid >> 1;
    const int brow = blockIdx.y * 128;
    const int bcol = blockIdx.x * 128;
    const int T = K >> 6;

    const uint32_t smb = smem_u32(sm);

    int am[8], akq[8];
    uint32_t adoff[8];
    #pragma unroll
    for (int p = 0; p < 8; p++) {
        const int c = tid + 128 * p;
        am[p]  = c >> 3;
        akq[p] = c & 7;
        adoff[p] = (uint32_t)(am[p] * 128 + (((akq[p] ^ (am[p] & 7)) << 4)));
    }

    float acc[4][8][4];
    #pragma unroll
    for (int mi = 0; mi < 4; mi++)
        #pragma unroll
        for (int ni = 0; ni < 8; ni++)
            #pragma unroll
            for (int e = 0; e < 4; e++) acc[mi][ni][e] = 0.f;

    auto issue_full = [&](int i, int stg) {
        const uint32_t dA = smb + (uint32_t)stg * STAGE_BYTES;
        const uint32_t dB = dA + 16384u;
        const int kbase = i * 64;
        #pragma unroll
        for (int p = 0; p < 8; p++) {
            cp16(dA + adoff[p], A  + (size_t)(brow + am[p]) * K + kbase + akq[p] * 8);
            cp16(dB + adoff[p], Bw + (size_t)(bcol + am[p]) * K + kbase + akq[p] * 8);
        }
        cp_commit();
    };

    const int a_r  = lane & 15;
    const int a_kq = lane >> 4;
    const int b_r  = (lane & 7) + ((lane >> 4) << 3);
    const int b_kq = (lane >> 3) & 1;
    uint32_t abase[4], axor[4], bbase[4], bxor[4];
    #pragma unroll
    for (int mi = 0; mi < 4; mi++) {
        const int row = wm * 64 + mi * 16 + a_r;
        abase[mi] = (uint32_t)(row * 128);
        axor[mi]  = (uint32_t)(row & 7);
    }
    #pragma unroll
    for (int g = 0; g < 4; g++) {
        const int row = wn * 64 + g * 16 + b_r;
        bbase[g] = (uint32_t)(16384 + row * 128);
        bxor[g]  = (uint32_t)(row & 7);
    }

    issue_full(0, 0);
    issue_full(1, 1);

    int stg = 0;
    for (int i = 0; i < T; i++) {
        if (i < T - 1) asm volatile("cp.async.wait_group 1;" ::: "memory");
        else           asm volatile("cp.async.wait_group 0;" ::: "memory");
        __syncthreads();

        const bool pf = (i + 2 < T);
        int nstg = stg + 2; if (nstg >= STAGES) nstg -= STAGES;
        const uint32_t dA2 = smb + (uint32_t)nstg * STAGE_BYTES;
        const uint32_t dB2 = dA2 + 16384u;
        const int kb2 = (i + 2) * 64;

        const uint32_t bufb = smb + (uint32_t)stg * STAGE_BYTES;

        #pragma unroll
        for (int s = 0; s < 4; s++) {
            if (pf) {
                #pragma unroll
                for (int q = 0; q < 2; q++) {
                    const int p = s * 2 + q;
                    cp16(dA2 + adoff[p],
                         A  + (size_t)(brow + am[p]) * K + kb2 + akq[p] * 8);
                    cp16(dB2 + adoff[p],
                         Bw + (size_t)(bcol + am[p]) * K + kb2 + akq[p] * 8);
                }
            }
            const uint32_t k0q = (uint32_t)(s * 2);
            uint32_t af[4][4], bfr[4][4];
            #pragma unroll
            for (int mi = 0; mi < 4; mi++)
                ldsm4(af[mi], bufb + abase[mi] + (((k0q + a_kq) ^ axor[mi]) << 4));
            #pragma unroll
            for (int g = 0; g < 4; g++)
                ldsm4(bfr[g], bufb + bbase[g] + (((k0q + b_kq) ^ bxor[g]) << 4));
            #pragma unroll
            for (int mi = 0; mi < 4; mi++)
                #pragma unroll
                for (int ni = 0; ni < 8; ni++)
                    mma16h(acc[mi][ni], af[mi],
                           bfr[ni >> 1][(ni & 1) * 2],
                           bfr[ni >> 1][(ni & 1) * 2 + 1]);
        }
        if (pf) cp_commit();
        if (++stg == STAGES) stg = 0;
    }

    #pragma unroll
    for (int mi = 0; mi < 4; mi++) {
        #pragma unroll
        for (int ni = 0; ni < 8; ni++) {
            const int r0  = brow + wm * 64 + mi * 16 + (lane >> 2);
            const int col = bcol + wn * 64 + ni * 8 + 2 * (lane & 3);
            const float b0 = bias[col], b1 = bias[col + 1];
            float v[4] = { acc[mi][ni][0] + b0, acc[mi][ni][1] + b1,
                           acc[mi][ni][2] + b0, acc[mi][ni][3] + b1 };
            if (EPI == EPI_RES) {
                float* C = (float*)Cout;
                const float2 x0 = *(const float2*)&resid[(size_t)r0 * N + col];
                const float2 x1 = *(const float2*)&resid[(size_t)(r0 + 8) * N + col];
                v[0] += x0.x; v[1] += x0.y; v[2] += x1.x; v[3] += x1.y;
                *(float2*)&C[(size_t)r0 * N + col]       = make_float2(v[0], v[1]);
                *(float2*)&C[(size_t)(r0 + 8) * N + col] = make_float2(v[2], v[3]);
            } else {
                if (EPI == EPI_G16) {
                    #pragma unroll
                    for (int e = 0; e < 4; e++)
                        v[e] = 0.5f * v[e] *
                               (1.0f + erff(v[e] * 0.70710678118654752f));
                }
                __half* C = (__half*)Cout;
                *(uint32_t*)&C[(size_t)r0 * N + col]       = f16pk(v[0], v[1]);
                *(uint32_t*)&C[(size_t)(r0 + 8) * N + col] = f16pk(v[2], v[3]);
            }
        }
    }
}

// ---------------- fp16 flash attention: 4 warps x 32 query rows ---------------
// grid (S/128, H, B), 128 threads; each warp owns 2 m16 q-tiles, so every
// K/V ldsm fragment feeds 2x the MMAs (halves L1/LDSM traffic per block).
#define ATT_ROWB 144             // 72 halves per row
#define ATT_BUFB (64 * ATT_ROWB) // 9216 bytes per matrix per stage

__global__ __launch_bounds__(128) void attn_mma(
    const __half* __restrict__ QKV, const int* __restrict__ mask,
    __half* __restrict__ O)
{
    __shared__ __align__(16) __half Ks[2][64][72];   // [buf][key][dk]
    __shared__ __align__(16) __half Vs[2][64][72];   // [buf][key][dk]

    const int b = blockIdx.z, h = blockIdx.y;
    const int tid = threadIdx.x, lane = tid & 31, wid = tid >> 5;
    const int gp = lane >> 2, tg = lane & 3;
    const int qrow0 = blockIdx.x * 128 + wid * 32 + gp;  // rows qrow0 + {0,8,16,24}

    const __half* Qb = QKV + (size_t)(b * S_) * QKV_S + h * DK_;
    const __half* Kb = Qb + D_;
    const __half* Vb = Qb + 2 * D_;

    const uint32_t ksb = smem_u32(&Ks[0][0][0]);
    const uint32_t vsb = smem_u32(&Vs[0][0][0]);

    // cp.async slots: 512 chunks of 16B per matrix, 4 per thread
    int ckey[4], cch[4];
    #pragma unroll
    for (int p = 0; p < 4; p++) {
        const int c = tid + 128 * p;
        ckey[p] = c >> 3; cch[p] = c & 7;
    }
    auto issue_kv = [&](int kt, int buf) {
        const uint32_t kb = ksb + (uint32_t)buf * ATT_BUFB;
        const uint32_t vb = vsb + (uint32_t)buf * ATT_BUFB;
        #pragma unroll
        for (int p = 0; p < 4; p++) {
            const size_t g = (size_t)(kt + ckey[p]) * QKV_S + cch[p] * 8;
            const uint32_t off = (uint32_t)(ckey[p] * ATT_ROWB + cch[p] * 16);
            cp16(kb + off, Kb + g);
            cp16(vb + off, Vb + g);
        }
        cp_commit();
    };

    const uint32_t kcon = (uint32_t)(((((lane >> 4) & 1) * 8 + (lane & 7)) * ATT_ROWB)
                                     + (((lane >> 3) & 1) * 8) * 2);
    const uint32_t vcon = (uint32_t)((((lane >> 3) & 1) * 8 + (lane & 7)) * ATT_ROWB
                                     + (((lane >> 4) & 1) * 8) * 2);

    // Q fragments for 2 q-tiles, 1/8 pre-folded (exact)
    uint32_t qf[2][4][4];
    {
        const uint32_t s125 = 0x30003000u;
        #pragma unroll
        for (int u = 0; u < 2; u++) {
            const __half* q0p = Qb + (size_t)(qrow0 + 16*u) * QKV_S;
            const __half* q1p = q0p + (size_t)8 * QKV_S;
            #pragma unroll
            for (int s = 0; s < 4; s++) {
                qf[u][s][0] = *(const uint32_t*)&q0p[16*s + 2*tg];
                qf[u][s][1] = *(const uint32_t*)&q1p[16*s + 2*tg];
                qf[u][s][2] = *(const uint32_t*)&q0p[16*s + 2*tg + 8];
                qf[u][s][3] = *(const uint32_t*)&q1p[16*s + 2*tg + 8];
                #pragma unroll
                for (int e = 0; e < 4; e++)
                    asm("mul.rn.f16x2 %0, %0, %1;" : "+r"(qf[u][s][e]) : "r"(s125));
            }
        }
    }

    float oa[2][8][4];
    #pragma unroll
    for (int u = 0; u < 2; u++)
        #pragma unroll
        for (int j = 0; j < 8; j++)
            #pragma unroll
            for (int e = 0; e < 4; e++) oa[u][j][e] = 0.f;
    float mc[2][2] = {{-1e30f, -1e30f}, {-1e30f, -1e30f}};
    float lc[2][2] = {{0.f, 0.f}, {0.f, 0.f}};

    const int* mr[2][2];
    #pragma unroll
    for (int u = 0; u < 2; u++) {
        mr[u][0] = mask + ((size_t)(b * S_ + qrow0 + 16*u)) * S_;
        mr[u][1] = mr[u][0] + (size_t)8 * S_;
    }

    issue_kv(0, 0);

    for (int it = 0; it < S_ / 64; it++) {
        asm volatile("cp.async.wait_group 0;" ::: "memory");
        __syncthreads();
        if (it + 1 < S_ / 64) issue_kv((it + 1) * 64, (it + 1) & 1);

        const uint32_t kbuf = ksb + (uint32_t)(it & 1) * ATT_BUFB;
        const uint32_t vbuf = vsb + (uint32_t)(it & 1) * ATT_BUFB;
        const int kt = it * 64;

        // S = (Q/8)·K^T — each K fragment feeds both q-tiles
        float sc[2][8][4];
        #pragma unroll
        for (int u = 0; u < 2; u++)
            #pragma unroll
            for (int j = 0; j < 8; j++)
                #pragma unroll
                for (int e = 0; e < 4; e++) sc[u][j][e] = 0.f;
        #pragma unroll
        for (int s = 0; s < 4; s++) {
            #pragma unroll
            for (int jj = 0; jj < 4; jj++) {
                uint32_t kf[4];
                ldsm4(kf, kbuf + (uint32_t)(jj * 2 * 8 * ATT_ROWB + s * 32) + kcon);
                #pragma unroll
                for (int u = 0; u < 2; u++) {
                    mma16h(sc[u][2*jj],     qf[u][s], kf[0], kf[1]);
                    mma16h(sc[u][2*jj + 1], qf[u][s], kf[2], kf[3]);
                }
            }
        }

        // mask + online softmax per q-tile
        #pragma unroll
        for (int u = 0; u < 2; u++) {
            #pragma unroll
            for (int j = 0; j < 8; j++) {
                const int2 mm0 = *(const int2*)&mr[u][0][kt + 8*j + 2*tg];
                const int2 mm1 = *(const int2*)&mr[u][1][kt + 8*j + 2*tg];
                if (mm0.x) sc[u][j][0] = -10000.0f;
                if (mm0.y) sc[u][j][1] = -10000.0f;
                if (mm1.x) sc[u][j][2] = -10000.0f;
                if (mm1.y) sc[u][j][3] = -10000.0f;
            }
            float t0 = -1e30f, t1 = -1e30f;
            #pragma unroll
            for (int j = 0; j < 8; j++) {
                t0 = fmaxf(t0, fmaxf(sc[u][j][0], sc[u][j][1]));
                t1 = fmaxf(t1, fmaxf(sc[u][j][2], sc[u][j][3]));
            }
            t0 = fmaxf(t0, __shfl_xor_sync(0xffffffffu, t0, 1));
            t0 = fmaxf(t0, __shfl_xor_sync(0xffffffffu, t0, 2));
            t1 = fmaxf(t1, __shfl_xor_sync(0xffffffffu, t1, 1));
            t1 = fmaxf(t1, __shfl_xor_sync(0xffffffffu, t1, 2));
            const float mn0 = fmaxf(mc[u][0], t0), mn1 = fmaxf(mc[u][1], t1);
            const float cr0 = __expf(mc[u][0] - mn0), cr1 = __expf(mc[u][1] - mn1);
            float ps0 = 0.f, ps1 = 0.f;
            #pragma unroll
            for (int j = 0; j < 8; j++) {
                sc[u][j][0] = __expf(sc[u][j][0] - mn0); ps0 += sc[u][j][0];
                sc[u][j][1] = __expf(sc[u][j][1] - mn0); ps0 += sc[u][j][1];
                sc[u][j][2] = __expf(sc[u][j][2] - mn1); ps1 += sc[u][j][2];
                sc[u][j][3] = __expf(sc[u][j][3] - mn1); ps1 += sc[u][j][3];
            }
            ps0 += __shfl_xor_sync(0xffffffffu, ps0, 1);
            ps0 += __shfl_xor_sync(0xffffffffu, ps0, 2);
            ps1 += __shfl_xor_sync(0xffffffffu, ps1, 1);
            ps1 += __shfl_xor_sync(0xffffffffu, ps1, 2);
            lc[u][0] = lc[u][0] * cr0 + ps0; mc[u][0] = mn0;
            lc[u][1] = lc[u][1] * cr1 + ps1; mc[u][1] = mn1;
            #pragma unroll
            for (int j = 0; j < 8; j++) {
                oa[u][j][0] *= cr0; oa[u][j][1] *= cr0;
                oa[u][j][2] *= cr1; oa[u][j][3] *= cr1;
            }
        }

        // P -> fp16 A fragments (layout identity)
        uint32_t pa[2][4][4];
        #pragma unroll
        for (int u = 0; u < 2; u++)
            #pragma unroll
            for (int t = 0; t < 4; t++) {
                pa[u][t][0] = f16pk(sc[u][2*t][0],     sc[u][2*t][1]);
                pa[u][t][1] = f16pk(sc[u][2*t][2],     sc[u][2*t][3]);
                pa[u][t][2] = f16pk(sc[u][2*t + 1][0], sc[u][2*t + 1][1]);
                pa[u][t][3] = f16pk(sc[u][2*t + 1][2], sc[u][2*t + 1][3]);
            }

        // O += P·V — each V fragment feeds both q-tiles
        #pragma unroll
        for (int t = 0; t < 4; t++) {
            #pragma unroll
            for (int jj = 0; jj < 4; jj++) {
                uint32_t vf[4];
                ldsm4t(vf, vbuf + (uint32_t)(t * 16 * ATT_ROWB + jj * 2 * 16) + vcon);
                #pragma unroll
                for (int u = 0; u < 2; u++) {
                    mma16h(oa[u][2*jj],     pa[u][t], vf[0], vf[1]);
                    mma16h(oa[u][2*jj + 1], pa[u][t], vf[2], vf[3]);
                }
            }
        }
    }

    #pragma unroll
    for (int u = 0; u < 2; u++) {
        const float inv0 = 1.0f / lc[u][0], inv1 = 1.0f / lc[u][1];
        __half* o0 = O + ((size_t)(b * S_ + qrow0 + 16*u)) * D_ + h * DK_;
        __half* o1 = o0 + (size_t)8 * D_;
        #pragma unroll
        for (int j = 0; j < 8; j++) {
            *(uint32_t*)&o0[8*j + 2*tg] = f16pk(oa[u][j][0] * inv0, oa[u][j][1] * inv0);
            *(uint32_t*)&o1[8*j + 2*tg] = f16pk(oa[u][j][2] * inv1, oa[u][j][3] * inv1);
        }
    }
}

// ---------------- launcher ----------------------------------------------------
extern "C" void kernel_launch(void* const* d_in, const int* in_sizes, int n_in,
                              void* d_out, int out_size)
{
    const float* x  = (const float*)d_in[0];
    const int*   mask = (const int*)d_in[1];
    const float* Wq = (const float*)d_in[2];  const float* bq = (const float*)d_in[3];
    const float* Wk = (const float*)d_in[4];  const float* bk = (const float*)d_in[5];
    const float* Wv = (const float*)d_in[6];  const float* bv = (const float*)d_in[7];
    const float* Wo = (const float*)d_in[8];  const float* bo = (const float*)d_in[9];
    const float* W1 = (const float*)d_in[10]; const float* b1 = (const float*)d_in[11];
    const float* W2 = (const float*)d_in[12]; const float* b2 = (const float*)d_in[13];
    const float* ga = (const float*)d_in[14]; const float* ba = (const float*)d_in[15];
    const float* gf = (const float*)d_in[16]; const float* bf = (const float*)d_in[17];
    float* out = (float*)d_out;

    __half *nxh, *qkvh, *ctxh, *nx2h, *hh, *wqkvh, *woh, *w1h, *w2h;
    float *x1, *bqkv;
    cudaGetSymbolAddress((void**)&nxh,   g_nxh);
    cudaGetSymbolAddress((void**)&qkvh,  g_qkvh);
    cudaGetSymbolAddress((void**)&ctxh,  g_ctxh);
    cudaGetSymbolAddress((void**)&x1,    g_x1);
    cudaGetSymbolAddress((void**)&nx2h,  g_nx2h);
    cudaGetSymbolAddress((void**)&hh,    g_hh);
    cudaGetSymbolAddress((void**)&wqkvh, g_wqkvh);
    cudaGetSymbolAddress((void**)&bqkv,  g_bqkv);
    cudaGetSymbolAddress((void**)&woh,   g_woh);
    cudaGetSymbolAddress((void**)&w1h,   g_w1h);
    cudaGetSymbolAddress((void**)&w2h,   g_w2h);

    cudaFuncSetAttribute(gemm_f16<EPI_H16>,
                         cudaFuncAttributeMaxDynamicSharedMemorySize, GEMM_SMEM);
    cudaFuncSetAttribute(gemm_f16<EPI_RES>,
                         cudaFuncAttributeMaxDynamicSharedMemorySize, GEMM_SMEM);
    cudaFuncSetAttribute(gemm_f16<EPI_G16>,
                         cudaFuncAttributeMaxDynamicSharedMemorySize, GEMM_SMEM);

    cvt_all_kernel<<<CVT_GRID, 256>>>(Wq, Wk, Wv, Wo, W1, W2, bq, bk, bv,
                                      wqkvh, woh, w1h, w2h, bqkv);
    ln_kernel<<<ROWS, 256>>>(x, ga, ba, nxh);

    dim3 gqkv(QKV_S / 128, ROWS / 128);
    gemm_f16<EPI_H16><<<gqkv, 128, GEMM_SMEM>>>(ROWS, QKV_S, D_, nxh, wqkvh,
                                                bqkv, nullptr, qkvh);

    attn_mma<<<dim3(S_ / 128, H_, B_), 128>>>(qkvh, mask, ctxh);

    dim3 g1(D_ / 128, ROWS / 128);
    gemm_f16<EPI_RES><<<g1, 128, GEMM_SMEM>>>(ROWS, D_, D_, ctxh, woh, bo, x, x1);

    ln_kernel<<<ROWS, 256>>>(x1, gf, bf, nx2h);

    dim3 g2(DFF_ / 128, ROWS / 128);
    gemm_f16<EPI_G16><<<g2, 128, GEMM_SMEM>>>(ROWS, DFF_, D_, nx2h, w1h, b1,
                                              nullptr, hh);

    gemm_f16<EPI_RES><<<g1, 128, GEMM_SMEM>>>(ROWS, D_, DFF_, hh, w2h, b2, x1, out);
}

// round 14
// speedup vs baseline: 1.7970x; 1.7970x over previous
#include <cuda_runtime.h>
#include <cuda_fp16.h>
#include <cstdint>

#define B_   2
#define S_   2048
#define D_   1024
#define H_   16
#define DK_  64
#define DFF_ 4096
#define ROWS (B_*S_)     // 4096
#define QKV_S (3*D_)     // 3072

// ---------------- scratch (device globals; no allocations allowed) ----------
__device__ __half g_nxh [ROWS*D_];      // LN1 out
__device__ __half g_qkvh[ROWS*QKV_S];   // packed q|k|v
__device__ __half g_ctxh[ROWS*D_];      // attention context
__device__ float  g_x1  [ROWS*D_];      // x after attn residual (fp32)
__device__ __half g_nx2h[ROWS*D_];      // LN2 out
__device__ __half g_hh  [ROWS*DFF_];    // ffn hidden
// fp16 weights
__device__ __half g_wqkvh[3*D_*D_];
__device__ float  g_bqkv[3*D_];
__device__ __half g_woh[D_*D_];
__device__ __half g_w1h[DFF_*D_], g_w2h[D_*DFF_];

// ---------------- helpers ----------------------------------------------------
__device__ __forceinline__ uint32_t smem_u32(const void* p) {
    uint32_t a;
    asm("{ .reg .u64 t; cvta.to.shared.u64 t, %1; cvt.u32.u64 %0, t; }"
        : "=r"(a) : "l"(p));
    return a;
}
__device__ __forceinline__ void cp16(uint32_t dst, const void* src) {
    asm volatile("cp.async.cg.shared.global [%0], [%1], 16;"
                 :: "r"(dst), "l"(src) : "memory");
}
__device__ __forceinline__ void cp_commit() {
    asm volatile("cp.async.commit_group;" ::: "memory");
}
__device__ __forceinline__ void ldsm4(uint32_t* r, uint32_t addr) {
    asm volatile("ldmatrix.sync.aligned.m8n8.x4.shared.b16 {%0,%1,%2,%3}, [%4];"
                 : "=r"(r[0]), "=r"(r[1]), "=r"(r[2]), "=r"(r[3]) : "r"(addr));
}
__device__ __forceinline__ void ldsm4t(uint32_t* r, uint32_t addr) {
    asm volatile("ldmatrix.sync.aligned.m8n8.x4.trans.shared.b16 {%0,%1,%2,%3}, [%4];"
                 : "=r"(r[0]), "=r"(r[1]), "=r"(r[2]), "=r"(r[3]) : "r"(addr));
}
// m16n8k16 fp16, fp32 accumulate
__device__ __forceinline__ void mma16h(float* c, const uint32_t* a,
                                       uint32_t b0, uint32_t b1) {
    asm volatile(
        "mma.sync.aligned.m16n8k16.row.col.f32.f16.f16.f32 "
        "{%0,%1,%2,%3}, {%4,%5,%6,%7}, {%8,%9}, {%0,%1,%2,%3};"
        : "+f"(c[0]), "+f"(c[1]), "+f"(c[2]), "+f"(c[3])
        : "r"(a[0]), "r"(a[1]), "r"(a[2]), "r"(a[3]), "r"(b0), "r"(b1));
}
// pack two f32 -> f16x2 (lo = first arg)
__device__ __forceinline__ uint32_t f16pk(float lo, float hi) {
    uint32_t r;
    asm("cvt.rn.f16x2.f32 %0, %1, %2;" : "=r"(r) : "f"(hi), "f"(lo));
    return r;
}
// packed f32x2 multiply (two independent rn muls; bit-identical to scalar)
__device__ __forceinline__ void mul2x(float* a01, float s) {
    unsigned long long v, sp;
    asm("mov.b64 %0, {%1, %2};" : "=l"(v) : "f"(a01[0]), "f"(a01[1]));
    asm("mov.b64 %0, {%1, %1};" : "=l"(sp) : "f"(s));
    asm("mul.rn.f32x2 %0, %0, %1;" : "+l"(v) : "l"(sp));
    asm("mov.b64 {%0, %1}, %2;" : "=f"(a01[0]), "=f"(a01[1]) : "l"(v));
}

// ---------------- fused weight conversion + bias pack (MLP=4) ----------------
#define NDD4 (D_*D_/4)
#define NDF4 (DFF_*D_/4)
#define CVT_F4   (4*NDD4 + 2*NDF4)
#define BIAS_F4  (3*D_/4)
#define CVT_UNITS (CVT_F4 + BIAS_F4)
#define CVT_GRID ((CVT_UNITS + 1023) / 1024)

__global__ __launch_bounds__(256) void cvt_all_kernel(
    const float* __restrict__ Wq, const float* __restrict__ Wk,
    const float* __restrict__ Wv, const float* __restrict__ Wo,
    const float* __restrict__ W1, const float* __restrict__ W2,
    const float* __restrict__ bq, const float* __restrict__ bk,
    const float* __restrict__ bv,
    __half* __restrict__ wqkv, __half* __restrict__ wo,
    __half* __restrict__ w1h, __half* __restrict__ w2h,
    float* __restrict__ bqkv)
{
    const int base = (blockIdx.x * 256 + threadIdx.x) * 4;
    #pragma unroll
    for (int p = 0; p < 4; p++) {
        const int i = base + p;
        if (i >= CVT_UNITS) break;
        if (i < CVT_F4) {
            const float4* src; __half* dst; int si, off;
            if (i < NDD4)             { src = (const float4*)Wq; si = i;               dst = wqkv; off = i; }
            else if (i < 2*NDD4)      { src = (const float4*)Wk; si = i - NDD4;        dst = wqkv; off = i; }
            else if (i < 3*NDD4)      { src = (const float4*)Wv; si = i - 2*NDD4;      dst = wqkv; off = i; }
            else if (i < 4*NDD4)      { src = (const float4*)Wo; si = i - 3*NDD4;      dst = wo;   off = si; }
            else if (i < 4*NDD4+NDF4) { src = (const float4*)W1; si = i - 4*NDD4;      dst = w1h;  off = si; }
            else                      { src = (const float4*)W2; si = i - 4*NDD4-NDF4; dst = w2h;  off = si; }
            float4 v = src[si];
            uint2 o;
            o.x = f16pk(v.x, v.y);
            o.y = f16pk(v.z, v.w);
            *(uint2*)&dst[(size_t)off * 4] = o;
        } else {
            const int j = i - CVT_F4;
            const float4* s; int sj;
            if (j < 256)      { s = (const float4*)bq; sj = j; }
            else if (j < 512) { s = (const float4*)bk; sj = j - 256; }
            else              { s = (const float4*)bv; sj = j - 512; }
            ((float4*)bqkv)[j] = s[sj];
        }
    }
}

// ---------------- LayerNorm (fp16 out) ----------------------------------------
__global__ __launch_bounds__(256) void ln_kernel(
    const float* __restrict__ x, const float* __restrict__ g,
    const float* __restrict__ bta, __half* __restrict__ out)
{
    const int row = blockIdx.x;
    const int t   = threadIdx.x;
    const float4* xr = (const float4*)(x + (size_t)row * D_);
    float4 v = xr[t];
    float s  = v.x + v.y + v.z + v.w;
    float s2 = v.x*v.x + v.y*v.y + v.z*v.z + v.w*v.w;
    #pragma unroll
    for (int o = 16; o > 0; o >>= 1) {
        s  += __shfl_xor_sync(0xffffffffu, s,  o);
        s2 += __shfl_xor_sync(0xffffffffu, s2, o);
    }
    __shared__ float rs[8], rs2[8];
    const int w = t >> 5;
    if ((t & 31) == 0) { rs[w] = s; rs2[w] = s2; }
    __syncthreads();
    s = 0.f; s2 = 0.f;
    #pragma unroll
    for (int i = 0; i < 8; i++) { s += rs[i]; s2 += rs2[i]; }
    const float mu   = s * (1.0f / D_);
    const float var  = s2 * (1.0f / D_) - mu * mu;
    const float rstd = rsqrtf(var + 1e-5f);
    float4 gg = ((const float4*)g)[t];
    float4 bb = ((const float4*)bta)[t];
    uint2 o;
    o.x = f16pk((v.x - mu) * rstd * gg.x + bb.x,
                (v.y - mu) * rstd * gg.y + bb.y);
    o.y = f16pk((v.z - mu) * rstd * gg.z + bb.z,
                (v.w - mu) * rstd * gg.w + bb.w);
    *(uint2*)(out + (size_t)row * D_ + t * 4) = o;
}

// ---------------- FP16 GEMM-NT: 4 warps, warp tile 64x64, K-tile 64 ----------
enum { EPI_H16 = 0, EPI_RES = 1, EPI_G16 = 2 };
#define STAGES 3
#define STAGE_BYTES 32768
#define GEMM_SMEM (STAGES * STAGE_BYTES)   // 96 KB

template <int EPI>
__global__ __launch_bounds__(128, 2) void gemm_f16(
    int M, int N, int K,
    const __half* __restrict__ A, const __half* __restrict__ Bw,
    const float* __restrict__ bias, const float* __restrict__ resid,
    void* __restrict__ Cout)
{
    extern __shared__ float sm[];
    const int tid  = threadIdx.x;
    const int lane = tid & 31;
    const int wid  = tid >> 5;
    const int wm = wid & 1;
    const int wn = wid >> 1;
    const int brow = blockIdx.y * 128;
    const int bcol = blockIdx.x * 128;
    const int T = K >> 6;

    const uint32_t smb = smem_u32(sm);

    int am[8], akq[8];
    uint32_t adoff[8];
    #pragma unroll
    for (int p = 0; p < 8; p++) {
        const int c = tid + 128 * p;
        am[p]  = c >> 3;
        akq[p] = c & 7;
        adoff[p] = (uint32_t)(am[p] * 128 + (((akq[p] ^ (am[p] & 7)) << 4)));
    }

    float acc[4][8][4];
    #pragma unroll
    for (int mi = 0; mi < 4; mi++)
        #pragma unroll
        for (int ni = 0; ni < 8; ni++)
            #pragma unroll
            for (int e = 0; e < 4; e++) acc[mi][ni][e] = 0.f;

    auto issue_full = [&](int i, int stg) {
        const uint32_t dA = smb + (uint32_t)stg * STAGE_BYTES;
        const uint32_t dB = dA + 16384u;
        const int kbase = i * 64;
        #pragma unroll
        for (int p = 0; p < 8; p++) {
            cp16(dA + adoff[p], A  + (size_t)(brow + am[p]) * K + kbase + akq[p] * 8);
            cp16(dB + adoff[p], Bw + (size_t)(bcol + am[p]) * K + kbase + akq[p] * 8);
        }
        cp_commit();
    };

    const int a_r  = lane & 15;
    const int a_kq = lane >> 4;
    const int b_r  = (lane & 7) + ((lane >> 4) << 3);
    const int b_kq = (lane >> 3) & 1;
    uint32_t abase[4], axor[4], bbase[4], bxor[4];
    #pragma unroll
    for (int mi = 0; mi < 4; mi++) {
        const int row = wm * 64 + mi * 16 + a_r;
        abase[mi] = (uint32_t)(row * 128);
        axor[mi]  = (uint32_t)(row & 7);
    }
    #pragma unroll
    for (int g = 0; g < 4; g++) {
        const int row = wn * 64 + g * 16 + b_r;
        bbase[g] = (uint32_t)(16384 + row * 128);
        bxor[g]  = (uint32_t)(row & 7);
    }

    issue_full(0, 0);
    issue_full(1, 1);

    int stg = 0;
    for (int i = 0; i < T; i++) {
        if (i < T - 1) asm volatile("cp.async.wait_group 1;" ::: "memory");
        else           asm volatile("cp.async.wait_group 0;" ::: "memory");
        __syncthreads();

        const bool pf = (i + 2 < T);
        int nstg = stg + 2; if (nstg >= STAGES) nstg -= STAGES;
        const uint32_t dA2 = smb + (uint32_t)nstg * STAGE_BYTES;
        const uint32_t dB2 = dA2 + 16384u;
        const int kb2 = (i + 2) * 64;

        const uint32_t bufb = smb + (uint32_t)stg * STAGE_BYTES;

        #pragma unroll
        for (int s = 0; s < 4; s++) {
            if (pf) {
                #pragma unroll
                for (int q = 0; q < 2; q++) {
                    const int p = s * 2 + q;
                    cp16(dA2 + adoff[p],
                         A  + (size_t)(brow + am[p]) * K + kb2 + akq[p] * 8);
                    cp16(dB2 + adoff[p],
                         Bw + (size_t)(bcol + am[p]) * K + kb2 + akq[p] * 8);
                }
            }
            const uint32_t k0q = (uint32_t)(s * 2);
            uint32_t af[4][4], bfr[4][4];
            #pragma unroll
            for (int mi = 0; mi < 4; mi++)
                ldsm4(af[mi], bufb + abase[mi] + (((k0q + a_kq) ^ axor[mi]) << 4));
            #pragma unroll
            for (int g = 0; g < 4; g++)
                ldsm4(bfr[g], bufb + bbase[g] + (((k0q + b_kq) ^ bxor[g]) << 4));
            #pragma unroll
            for (int mi = 0; mi < 4; mi++)
                #pragma unroll
                for (int ni = 0; ni < 8; ni++)
                    mma16h(acc[mi][ni], af[mi],
                           bfr[ni >> 1][(ni & 1) * 2],
                           bfr[ni >> 1][(ni & 1) * 2 + 1]);
        }
        if (pf) cp_commit();
        if (++stg == STAGES) stg = 0;
    }

    #pragma unroll
    for (int mi = 0; mi < 4; mi++) {
        #pragma unroll
        for (int ni = 0; ni < 8; ni++) {
            const int r0  = brow + wm * 64 + mi * 16 + (lane >> 2);
            const int col = bcol + wn * 64 + ni * 8 + 2 * (lane & 3);
            const float b0 = bias[col], b1 = bias[col + 1];
            float v[4] = { acc[mi][ni][0] + b0, acc[mi][ni][1] + b1,
                           acc[mi][ni][2] + b0, acc[mi][ni][3] + b1 };
            if (EPI == EPI_RES) {
                float* C = (float*)Cout;
                const float2 x0 = *(const float2*)&resid[(size_t)r0 * N + col];
                const float2 x1 = *(const float2*)&resid[(size_t)(r0 + 8) * N + col];
                v[0] += x0.x; v[1] += x0.y; v[2] += x1.x; v[3] += x1.y;
                *(float2*)&C[(size_t)r0 * N + col]       = make_float2(v[0], v[1]);
                *(float2*)&C[(size_t)(r0 + 8) * N + col] = make_float2(v[2], v[3]);
            } else {
                if (EPI == EPI_G16) {
                    #pragma unroll
                    for (int e = 0; e < 4; e++)
                        v[e] = 0.5f * v[e] *
                               (1.0f + erff(v[e] * 0.70710678118654752f));
                }
                __half* C = (__half*)Cout;
                *(uint32_t*)&C[(size_t)r0 * N + col]       = f16pk(v[0], v[1]);
                *(uint32_t*)&C[(size_t)(r0 + 8) * N + col] = f16pk(v[2], v[3]);
            }
        }
    }
}

// ---------------- fp16 flash attention (R12 config: 256 thr, 16 rows/warp) ---
#define ATT_ROWB 144             // 72 halves per row
#define ATT_BUFB (64 * ATT_ROWB) // 9216 bytes per matrix per stage

__global__ __launch_bounds__(256) void attn_mma(
    const __half* __restrict__ QKV, const int* __restrict__ mask,
    __half* __restrict__ O)
{
    __shared__ __align__(16) __half Ks[2][64][72];   // [buf][key][dk]
    __shared__ __align__(16) __half Vs[2][64][72];   // [buf][key][dk]

    const int b = blockIdx.z, h = blockIdx.y;
    const int tid = threadIdx.x, lane = tid & 31, wid = tid >> 5;
    const int gp = lane >> 2, tg = lane & 3;
    const int qrow0 = blockIdx.x * 128 + wid * 16 + gp;

    const __half* Qb = QKV + (size_t)(b * S_) * QKV_S + h * DK_;
    const __half* Kb = Qb + D_;
    const __half* Vb = Qb + 2 * D_;

    const uint32_t ksb = smem_u32(&Ks[0][0][0]);
    const uint32_t vsb = smem_u32(&Vs[0][0][0]);

    int ckey[2], cch[2];
    #pragma unroll
    for (int p = 0; p < 2; p++) {
        const int c = tid + 256 * p;
        ckey[p] = c >> 3; cch[p] = c & 7;
    }
    auto issue_kv = [&](int kt, int buf) {
        const uint32_t kb = ksb + (uint32_t)buf * ATT_BUFB;
        const uint32_t vb = vsb + (uint32_t)buf * ATT_BUFB;
        #pragma unroll
        for (int p = 0; p < 2; p++) {
            const size_t g = (size_t)(kt + ckey[p]) * QKV_S + cch[p] * 8;
            const uint32_t off = (uint32_t)(ckey[p] * ATT_ROWB + cch[p] * 16);
            cp16(kb + off, Kb + g);
            cp16(vb + off, Vb + g);
        }
        cp_commit();
    };

    const uint32_t kcon = (uint32_t)(((((lane >> 4) & 1) * 8 + (lane & 7)) * ATT_ROWB)
                                     + (((lane >> 3) & 1) * 8) * 2);
    const uint32_t vcon = (uint32_t)((((lane >> 3) & 1) * 8 + (lane & 7)) * ATT_ROWB
                                     + (((lane >> 4) & 1) * 8) * 2);

    // Q fragments with 1/8 folded in (fp16 0.125 = 0x3000, exact power of 2)
    uint32_t qf[4][4];
    {
        const __half* q0p = Qb + (size_t)qrow0 * QKV_S;
        const __half* q1p = q0p + (size_t)8 * QKV_S;
        const uint32_t s125 = 0x30003000u;
        #pragma unroll
        for (int s = 0; s < 4; s++) {
            qf[s][0] = *(const uint32_t*)&q0p[16*s + 2*tg];
            qf[s][1] = *(const uint32_t*)&q1p[16*s + 2*tg];
            qf[s][2] = *(const uint32_t*)&q0p[16*s + 2*tg + 8];
            qf[s][3] = *(const uint32_t*)&q1p[16*s + 2*tg + 8];
            #pragma unroll
            for (int e = 0; e < 4; e++)
                asm("mul.rn.f16x2 %0, %0, %1;" : "+r"(qf[s][e]) : "r"(s125));
        }
    }

    float oa[8][4];
    #pragma unroll
    for (int j = 0; j < 8; j++)
        #pragma unroll
        for (int e = 0; e < 4; e++) oa[j][e] = 0.f;
    float m0c = -1e30f, m1c = -1e30f, l0 = 0.f, l1 = 0.f;

    const int* mr0 = mask + ((size_t)(b * S_ + qrow0)) * S_;
    const int* mr1 = mr0 + (size_t)8 * S_;

    issue_kv(0, 0);

    for (int it = 0; it < S_ / 64; it++) {
        asm volatile("cp.async.wait_group 0;" ::: "memory");
        __syncthreads();
        if (it + 1 < S_ / 64) issue_kv((it + 1) * 64, (it + 1) & 1);

        const uint32_t kbuf = ksb + (uint32_t)(it & 1) * ATT_BUFB;
        const uint32_t vbuf = vsb + (uint32_t)(it & 1) * ATT_BUFB;
        const int kt = it * 64;

        // S = (Q/8)·K^T
        float sc[8][4];
        #pragma unroll
        for (int j = 0; j < 8; j++)
            #pragma unroll
            for (int e = 0; e < 4; e++) sc[j][e] = 0.f;
        #pragma unroll
        for (int s = 0; s < 4; s++) {
            #pragma unroll
            for (int jj = 0; jj < 4; jj++) {
                uint32_t kf[4];
                ldsm4(kf, kbuf + (uint32_t)(jj * 2 * 8 * ATT_ROWB + s * 32) + kcon);
                mma16h(sc[2*jj],     qf[s], kf[0], kf[1]);
                mma16h(sc[2*jj + 1], qf[s], kf[2], kf[3]);
            }
        }

        // mask (scale already folded into Q)
        #pragma unroll
        for (int j = 0; j < 8; j++) {
            const int2 mm0 = *(const int2*)&mr0[kt + 8*j + 2*tg];
            const int2 mm1 = *(const int2*)&mr1[kt + 8*j + 2*tg];
            if (mm0.x) sc[j][0] = -10000.0f;
            if (mm0.y) sc[j][1] = -10000.0f;
            if (mm1.x) sc[j][2] = -10000.0f;
            if (mm1.y) sc[j][3] = -10000.0f;
        }

        // online softmax
        float t0 = -1e30f, t1 = -1e30f;
        #pragma unroll
        for (int j = 0; j < 8; j++) {
            t0 = fmaxf(t0, fmaxf(sc[j][0], sc[j][1]));
            t1 = fmaxf(t1, fmaxf(sc[j][2], sc[j][3]));
        }
        t0 = fmaxf(t0, __shfl_xor_sync(0xffffffffu, t0, 1));
        t0 = fmaxf(t0, __shfl_xor_sync(0xffffffffu, t0, 2));
        t1 = fmaxf(t1, __shfl_xor_sync(0xffffffffu, t1, 1));
        t1 = fmaxf(t1, __shfl_xor_sync(0xffffffffu, t1, 2));
        const float mn0 = fmaxf(m0c, t0), mn1 = fmaxf(m1c, t1);
        const float cr0 = __expf(m0c - mn0), cr1 = __expf(m1c - mn1);
        float ps0 = 0.f, ps1 = 0.f;
        #pragma unroll
        for (int j = 0; j < 8; j++) {
            sc[j][0] = __expf(sc[j][0] - mn0); ps0 += sc[j][0];
            sc[j][1] = __expf(sc[j][1] - mn0); ps0 += sc[j][1];
            sc[j][2] = __expf(sc[j][2] - mn1); ps1 += sc[j][2];
            sc[j][3] = __expf(sc[j][3] - mn1); ps1 += sc[j][3];
        }
        ps0 += __shfl_xor_sync(0xffffffffu, ps0, 1);
        ps0 += __shfl_xor_sync(0xffffffffu, ps0, 2);
        ps1 += __shfl_xor_sync(0xffffffffu, ps1, 1);
        ps1 += __shfl_xor_sync(0xffffffffu, ps1, 2);
        l0 = l0 * cr0 + ps0; m0c = mn0;
        l1 = l1 * cr1 + ps1; m1c = mn1;
        #pragma unroll
        for (int j = 0; j < 8; j++) {
            mul2x(&oa[j][0], cr0);   // packed rescale, bit-identical
            mul2x(&oa[j][2], cr1);
        }

        // P -> fp16 A fragments (layout identity)
        uint32_t pa[4][4];
        #pragma unroll
        for (int t = 0; t < 4; t++) {
            pa[t][0] = f16pk(sc[2*t][0],     sc[2*t][1]);
            pa[t][1] = f16pk(sc[2*t][2],     sc[2*t][3]);
            pa[t][2] = f16pk(sc[2*t + 1][0], sc[2*t + 1][1]);
            pa[t][3] = f16pk(sc[2*t + 1][2], sc[2*t + 1][3]);
        }

        // O += P·V via ldmatrix.trans fragments
        #pragma unroll
        for (int t = 0; t < 4; t++) {
            #pragma unroll
            for (int jj = 0; jj < 4; jj++) {
                uint32_t vf[4];
                ldsm4t(vf, vbuf + (uint32_t)(t * 16 * ATT_ROWB + jj * 2 * 16) + vcon);
                mma16h(oa[2*jj],     pa[t], vf[0], vf[1]);
                mma16h(oa[2*jj + 1], pa[t], vf[2], vf[3]);
            }
        }
    }

    const float inv0 = 1.0f / l0, inv1 = 1.0f / l1;
    __half* o0 = O + ((size_t)(b * S_ + qrow0)) * D_ + h * DK_;
    __half* o1 = o0 + (size_t)8 * D_;
    #pragma unroll
    for (int j = 0; j < 8; j++) {
        *(uint32_t*)&o0[8*j + 2*tg] = f16pk(oa[j][0] * inv0, oa[j][1] * inv0);
        *(uint32_t*)&o1[8*j + 2*tg] = f16pk(oa[j][2] * inv1, oa[j][3] * inv1);
    }
}

// ---------------- launcher ----------------------------------------------------
extern "C" void kernel_launch(void* const* d_in, const int* in_sizes, int n_in,
                              void* d_out, int out_size)
{
    const float* x  = (const float*)d_in[0];
    const int*   mask = (const int*)d_in[1];
    const float* Wq = (const float*)d_in[2];  const float* bq = (const float*)d_in[3];
    const float* Wk = (const float*)d_in[4];  const float* bk = (const float*)d_in[5];
    const float* Wv = (const float*)d_in[6];  const float* bv = (const float*)d_in[7];
    const float* Wo = (const float*)d_in[8];  const float* bo = (const float*)d_in[9];
    const float* W1 = (const float*)d_in[10]; const float* b1 = (const float*)d_in[11];
    const float* W2 = (const float*)d_in[12]; const float* b2 = (const float*)d_in[13];
    const float* ga = (const float*)d_in[14]; const float* ba = (const float*)d_in[15];
    const float* gf = (const float*)d_in[16]; const float* bf = (const float*)d_in[17];
    float* out = (float*)d_out;

    __half *nxh, *qkvh, *ctxh, *nx2h, *hh, *wqkvh, *woh, *w1h, *w2h;
    float *x1, *bqkv;
    cudaGetSymbolAddress((void**)&nxh,   g_nxh);
    cudaGetSymbolAddress((void**)&qkvh,  g_qkvh);
    cudaGetSymbolAddress((void**)&ctxh,  g_ctxh);
    cudaGetSymbolAddress((void**)&x1,    g_x1);
    cudaGetSymbolAddress((void**)&nx2h,  g_nx2h);
    cudaGetSymbolAddress((void**)&hh,    g_hh);
    cudaGetSymbolAddress((void**)&wqkvh, g_wqkvh);
    cudaGetSymbolAddress((void**)&bqkv,  g_bqkv);
    cudaGetSymbolAddress((void**)&woh,   g_woh);
    cudaGetSymbolAddress((void**)&w1h,   g_w1h);
    cudaGetSymbolAddress((void**)&w2h,   g_w2h);

    cudaFuncSetAttribute(gemm_f16<EPI_H16>,
                         cudaFuncAttributeMaxDynamicSharedMemorySize, GEMM_SMEM);
    cudaFuncSetAttribute(gemm_f16<EPI_RES>,
                         cudaFuncAttributeMaxDynamicSharedMemorySize, GEMM_SMEM);
    cudaFuncSetAttribute(gemm_f16<EPI_G16>,
                         cudaFuncAttributeMaxDynamicSharedMemorySize, GEMM_SMEM);

    cvt_all_kernel<<<CVT_GRID, 256>>>(Wq, Wk, Wv, Wo, W1, W2, bq, bk, bv,
                                      wqkvh, woh, w1h, w2h, bqkv);
    ln_kernel<<<ROWS, 256>>>(x, ga, ba, nxh);

    dim3 gqkv(QKV_S / 128, ROWS / 128);
    gemm_f16<EPI_H16><<<gqkv, 128, GEMM_SMEM>>>(ROWS, QKV_S, D_, nxh, wqkvh,
                                                bqkv, nullptr, qkvh);

    attn_mma<<<dim3(S_ / 128, H_, B_), 256>>>(qkvh, mask, ctxh);

    dim3 g1(D_ / 128, ROWS / 128);
    gemm_f16<EPI_RES><<<g1, 128, GEMM_SMEM>>>(ROWS, D_, D_, ctxh, woh, bo, x, x1);

    ln_kernel<<<ROWS, 256>>>(x1, gf, bf, nx2h);

    dim3 g2(DFF_ / 128, ROWS / 128);
    gemm_f16<EPI_G16><<<g2, 128, GEMM_SMEM>>>(ROWS, DFF_, D_, nx2h, w1h, b1,
                                              nullptr, hh);

    gemm_f16<EPI_RES><<<g1, 128, GEMM_SMEM>>>(ROWS, D_, DFF_, hh, w2h, b2, x1, out);
}

// round 17
// speedup vs baseline: 1.8281x; 1.0173x over previous
#include <cuda_runtime.h>
#include <cuda_fp16.h>
#include <cstdint>

#define B_   2
#define S_   2048
#define D_   1024
#define H_   16
#define DK_  64
#define DFF_ 4096
#define ROWS (B_*S_)     // 4096
#define QKV_S (3*D_)     // 3072
#define MW   (S_/32)     // 64 mask words per row

// ---------------- scratch (device globals; no allocations allowed) ----------
__device__ __half g_nxh [ROWS*D_];      // LN1 out
__device__ __half g_qkvh[ROWS*QKV_S];   // packed q|k|v
__device__ __half g_ctxh[ROWS*D_];      // attention context
__device__ float  g_x1  [ROWS*D_];      // x after attn residual (fp32)
__device__ __half g_nx2h[ROWS*D_];      // LN2 out
__device__ __half g_hh  [ROWS*DFF_];    // ffn hidden
__device__ uint32_t g_mbits[ROWS*MW];   // packed mask bits (1 bit / element)
// fp16 weights
__device__ __half g_wqkvh[3*D_*D_];
__device__ float  g_bqkv[3*D_];
__device__ __half g_woh[D_*D_];
__device__ __half g_w1h[DFF_*D_], g_w2h[D_*DFF_];

// ---------------- helpers ----------------------------------------------------
__device__ __forceinline__ uint32_t smem_u32(const void* p) {
    uint32_t a;
    asm("{ .reg .u64 t; cvta.to.shared.u64 t, %1; cvt.u32.u64 %0, t; }"
        : "=r"(a) : "l"(p));
    return a;
}
__device__ __forceinline__ void cp16(uint32_t dst, const void* src) {
    asm volatile("cp.async.cg.shared.global [%0], [%1], 16;"
                 :: "r"(dst), "l"(src) : "memory");
}
__device__ __forceinline__ void cp_commit() {
    asm volatile("cp.async.commit_group;" ::: "memory");
}
__device__ __forceinline__ void ldsm4(uint32_t* r, uint32_t addr) {
    asm volatile("ldmatrix.sync.aligned.m8n8.x4.shared.b16 {%0,%1,%2,%3}, [%4];"
                 : "=r"(r[0]), "=r"(r[1]), "=r"(r[2]), "=r"(r[3]) : "r"(addr));
}
__device__ __forceinline__ void ldsm4t(uint32_t* r, uint32_t addr) {
    asm volatile("ldmatrix.sync.aligned.m8n8.x4.trans.shared.b16 {%0,%1,%2,%3}, [%4];"
                 : "=r"(r[0]), "=r"(r[1]), "=r"(r[2]), "=r"(r[3]) : "r"(addr));
}
// m16n8k16 fp16, fp32 accumulate
__device__ __forceinline__ void mma16h(float* c, const uint32_t* a,
                                       uint32_t b0, uint32_t b1) {
    asm volatile(
        "mma.sync.aligned.m16n8k16.row.col.f32.f16.f16.f32 "
        "{%0,%1,%2,%3}, {%4,%5,%6,%7}, {%8,%9}, {%0,%1,%2,%3};"
        : "+f"(c[0]), "+f"(c[1]), "+f"(c[2]), "+f"(c[3])
        : "r"(a[0]), "r"(a[1]), "r"(a[2]), "r"(a[3]), "r"(b0), "r"(b1));
}
// pack two f32 -> f16x2 (lo = first arg)
__device__ __forceinline__ uint32_t f16pk(float lo, float hi) {
    uint32_t r;
    asm("cvt.rn.f16x2.f32 %0, %1, %2;" : "=r"(r) : "f"(hi), "f"(lo));
    return r;
}
// packed f32x2 multiply (two independent rn muls; bit-identical to scalar)
__device__ __forceinline__ void mul2x(float* a01, float s) {
    unsigned long long v, sp;
    asm("mov.b64 %0, {%1, %2};" : "=l"(v) : "f"(a01[0]), "f"(a01[1]));
    asm("mov.b64 %0, {%1, %1};" : "=l"(sp) : "f"(s));
    asm("mul.rn.f32x2 %0, %0, %1;" : "+l"(v) : "l"(sp));
    asm("mov.b64 {%0, %1}, %2;" : "=f"(a01[0]), "=f"(a01[1]) : "l"(v));
}

// ---------------- mask -> bitmask pre-pass ------------------------------------
// one warp per 32-element word; ballot packs mask!=0 into 1 bit each.
__global__ __launch_bounds__(256) void mask_bits_kernel(
    const int* __restrict__ mask, uint32_t* __restrict__ bits)
{
    const int w = blockIdx.x * 8 + (threadIdx.x >> 5);
    const int lane = threadIdx.x & 31;
    const int v = mask[(size_t)w * 32 + lane];
    const uint32_t bmask = __ballot_sync(0xffffffffu, v != 0);
    if (lane == 0) bits[w] = bmask;
}

// ---------------- fused weight conversion + bias pack (MLP=4) ----------------
#define NDD4 (D_*D_/4)
#define NDF4 (DFF_*D_/4)
#define CVT_F4   (4*NDD4 + 2*NDF4)
#define BIAS_F4  (3*D_/4)
#define CVT_UNITS (CVT_F4 + BIAS_F4)
#define CVT_GRID ((CVT_UNITS + 1023) / 1024)

__global__ __launch_bounds__(256) void cvt_all_kernel(
    const float* __restrict__ Wq, const float* __restrict__ Wk,
    const float* __restrict__ Wv, const float* __restrict__ Wo,
    const float* __restrict__ W1, const float* __restrict__ W2,
    const float* __restrict__ bq, const float* __restrict__ bk,
    const float* __restrict__ bv,
    __half* __restrict__ wqkv, __half* __restrict__ wo,
    __half* __restrict__ w1h, __half* __restrict__ w2h,
    float* __restrict__ bqkv)
{
    const int base = (blockIdx.x * 256 + threadIdx.x) * 4;
    #pragma unroll
    for (int p = 0; p < 4; p++) {
        const int i = base + p;
        if (i >= CVT_UNITS) break;
        if (i < CVT_F4) {
            const float4* src; __half* dst; int si, off;
            if (i < NDD4)             { src = (const float4*)Wq; si = i;               dst = wqkv; off = i; }
            else if (i < 2*NDD4)      { src = (const float4*)Wk; si = i - NDD4;        dst = wqkv; off = i; }
            else if (i < 3*NDD4)      { src = (const float4*)Wv; si = i - 2*NDD4;      dst = wqkv; off = i; }
            else if (i < 4*NDD4)      { src = (const float4*)Wo; si = i - 3*NDD4;      dst = wo;   off = si; }
            else if (i < 4*NDD4+NDF4) { src = (const float4*)W1; si = i - 4*NDD4;      dst = w1h;  off = si; }
            else                      { src = (const float4*)W2; si = i - 4*NDD4-NDF4; dst = w2h;  off = si; }
            float4 v = src[si];
            uint2 o;
            o.x = f16pk(v.x, v.y);
            o.y = f16pk(v.z, v.w);
            *(uint2*)&dst[(size_t)off * 4] = o;
        } else {
            const int j = i - CVT_F4;
            const float4* s; int sj;
            if (j < 256)      { s = (const float4*)bq; sj = j; }
            else if (j < 512) { s = (const float4*)bk; sj = j - 256; }
            else              { s = (const float4*)bv; sj = j - 512; }
            ((float4*)bqkv)[j] = s[sj];
        }
    }
}

// ---------------- LayerNorm (fp16 out) ----------------------------------------
__global__ __launch_bounds__(256) void ln_kernel(
    const float* __restrict__ x, const float* __restrict__ g,
    const float* __restrict__ bta, __half* __restrict__ out)
{
    const int row = blockIdx.x;
    const int t   = threadIdx.x;
    const float4* xr = (const float4*)(x + (size_t)row * D_);
    float4 v = xr[t];
    float s  = v.x + v.y + v.z + v.w;
    float s2 = v.x*v.x + v.y*v.y + v.z*v.z + v.w*v.w;
    #pragma unroll
    for (int o = 16; o > 0; o >>= 1) {
        s  += __shfl_xor_sync(0xffffffffu, s,  o);
        s2 += __shfl_xor_sync(0xffffffffu, s2, o);
    }
    __shared__ float rs[8], rs2[8];
    const int w = t >> 5;
    if ((t & 31) == 0) { rs[w] = s; rs2[w] = s2; }
    __syncthreads();
    s = 0.f; s2 = 0.f;
    #pragma unroll
    for (int i = 0; i < 8; i++) { s += rs[i]; s2 += rs2[i]; }
    const float mu   = s * (1.0f / D_);
    const float var  = s2 * (1.0f / D_) - mu * mu;
    const float rstd = rsqrtf(var + 1e-5f);
    float4 gg = ((const float4*)g)[t];
    float4 bb = ((const float4*)bta)[t];
    uint2 o;
    o.x = f16pk((v.x - mu) * rstd * gg.x + bb.x,
                (v.y - mu) * rstd * gg.y + bb.y);
    o.y = f16pk((v.z - mu) * rstd * gg.z + bb.z,
                (v.w - mu) * rstd * gg.w + bb.w);
    *(uint2*)(out + (size_t)row * D_ + t * 4) = o;
}

// ---------------- FP16 GEMM-NT: 4 warps, warp tile 64x64, K-tile 64 ----------
enum { EPI_H16 = 0, EPI_RES = 1, EPI_G16 = 2 };
#define STAGES 3
#define STAGE_BYTES 32768
#define GEMM_SMEM (STAGES * STAGE_BYTES)   // 96 KB

template <int EPI>
__global__ __launch_bounds__(128, 2) void gemm_f16(
    int M, int N, int K,
    const __half* __restrict__ A, const __half* __restrict__ Bw,
    const float* __restrict__ bias, const float* __restrict__ resid,
    void* __restrict__ Cout)
{
    extern __shared__ float sm[];
    const int tid  = threadIdx.x;
    const int lane = tid & 31;
    const int wid  = tid >> 5;
    const int wm = wid & 1;
    const int wn = wid >> 1;
    const int brow = blockIdx.y * 128;
    const int bcol = blockIdx.x * 128;
    const int T = K >> 6;

    const uint32_t smb = smem_u32(sm);

    int am[8], akq[8];
    uint32_t adoff[8];
    #pragma unroll
    for (int p = 0; p < 8; p++) {
        const int c = tid + 128 * p;
        am[p]  = c >> 3;
        akq[p] = c & 7;
        adoff[p] = (uint32_t)(am[p] * 128 + (((akq[p] ^ (am[p] & 7)) << 4)));
    }

    float acc[4][8][4];
    #pragma unroll
    for (int mi = 0; mi < 4; mi++)
        #pragma unroll
        for (int ni = 0; ni < 8; ni++)
            #pragma unroll
            for (int e = 0; e < 4; e++) acc[mi][ni][e] = 0.f;

    auto issue_full = [&](int i, int stg) {
        const uint32_t dA = smb + (uint32_t)stg * STAGE_BYTES;
        const uint32_t dB = dA + 16384u;
        const int kbase = i * 64;
        #pragma unroll
        for (int p = 0; p < 8; p++) {
            cp16(dA + adoff[p], A  + (size_t)(brow + am[p]) * K + kbase + akq[p] * 8);
            cp16(dB + adoff[p], Bw + (size_t)(bcol + am[p]) * K + kbase + akq[p] * 8);
        }
        cp_commit();
    };

    const int a_r  = lane & 15;
    const int a_kq = lane >> 4;
    const int b_r  = (lane & 7) + ((lane >> 4) << 3);
    const int b_kq = (lane >> 3) & 1;
    uint32_t abase[4], axor[4], bbase[4], bxor[4];
    #pragma unroll
    for (int mi = 0; mi < 4; mi++) {
        const int row = wm * 64 + mi * 16 + a_r;
        abase[mi] = (uint32_t)(row * 128);
        axor[mi]  = (uint32_t)(row & 7);
    }
    #pragma unroll
    for (int g = 0; g < 4; g++) {
        const int row = wn * 64 + g * 16 + b_r;
        bbase[g] = (uint32_t)(16384 + row * 128);
        bxor[g]  = (uint32_t)(row & 7);
    }

    issue_full(0, 0);
    issue_full(1, 1);

    int stg = 0;
    for (int i = 0; i < T; i++) {
        if (i < T - 1) asm volatile("cp.async.wait_group 1;" ::: "memory");
        else           asm volatile("cp.async.wait_group 0;" ::: "memory");
        __syncthreads();

        const bool pf = (i + 2 < T);
        int nstg = stg + 2; if (nstg >= STAGES) nstg -= STAGES;
        const uint32_t dA2 = smb + (uint32_t)nstg * STAGE_BYTES;
        const uint32_t dB2 = dA2 + 16384u;
        const int kb2 = (i + 2) * 64;

        const uint32_t bufb = smb + (uint32_t)stg * STAGE_BYTES;

        #pragma unroll
        for (int s = 0; s < 4; s++) {
            if (pf) {
                #pragma unroll
                for (int q = 0; q < 2; q++) {
                    const int p = s * 2 + q;
                    cp16(dA2 + adoff[p],
                         A  + (size_t)(brow + am[p]) * K + kb2 + akq[p] * 8);
                    cp16(dB2 + adoff[p],
                         Bw + (size_t)(bcol + am[p]) * K + kb2 + akq[p] * 8);
                }
            }
            const uint32_t k0q = (uint32_t)(s * 2);
            uint32_t af[4][4], bfr[4][4];
            #pragma unroll
            for (int mi = 0; mi < 4; mi++)
                ldsm4(af[mi], bufb + abase[mi] + (((k0q + a_kq) ^ axor[mi]) << 4));
            #pragma unroll
            for (int g = 0; g < 4; g++)
                ldsm4(bfr[g], bufb + bbase[g] + (((k0q + b_kq) ^ bxor[g]) << 4));
            #pragma unroll
            for (int mi = 0; mi < 4; mi++)
                #pragma unroll
                for (int ni = 0; ni < 8; ni++)
                    mma16h(acc[mi][ni], af[mi],
                           bfr[ni >> 1][(ni & 1) * 2],
                           bfr[ni >> 1][(ni & 1) * 2 + 1]);
        }
        if (pf) cp_commit();
        if (++stg == STAGES) stg = 0;
    }

    #pragma unroll
    for (int mi = 0; mi < 4; mi++) {
        #pragma unroll
        for (int ni = 0; ni < 8; ni++) {
            const int r0  = brow + wm * 64 + mi * 16 + (lane >> 2);
            const int col = bcol + wn * 64 + ni * 8 + 2 * (lane & 3);
            const float b0 = bias[col], b1 = bias[col + 1];
            float v[4] = { acc[mi][ni][0] + b0, acc[mi][ni][1] + b1,
                           acc[mi][ni][2] + b0, acc[mi][ni][3] + b1 };
            if (EPI == EPI_RES) {
                float* C = (float*)Cout;
                const float2 x0 = *(const float2*)&resid[(size_t)r0 * N + col];
                const float2 x1 = *(const float2*)&resid[(size_t)(r0 + 8) * N + col];
                v[0] += x0.x; v[1] += x0.y; v[2] += x1.x; v[3] += x1.y;
                *(float2*)&C[(size_t)r0 * N + col]       = make_float2(v[0], v[1]);
                *(float2*)&C[(size_t)(r0 + 8) * N + col] = make_float2(v[2], v[3]);
            } else {
                if (EPI == EPI_G16) {
                    #pragma unroll
                    for (int e = 0; e < 4; e++)
                        v[e] = 0.5f * v[e] *
                               (1.0f + erff(v[e] * 0.70710678118654752f));
                }
                __half* C = (__half*)Cout;
                *(uint32_t*)&C[(size_t)r0 * N + col]       = f16pk(v[0], v[1]);
                *(uint32_t*)&C[(size_t)(r0 + 8) * N + col] = f16pk(v[2], v[3]);
            }
        }
    }
}

// ---------------- fp16 flash attention (bitmask; 256 thr, 16 rows/warp) ------
#define ATT_ROWB 144             // 72 halves per row
#define ATT_BUFB (64 * ATT_ROWB) // 9216 bytes per matrix per stage

__global__ __launch_bounds__(256) void attn_mma(
    const __half* __restrict__ QKV, const uint32_t* __restrict__ mbits,
    __half* __restrict__ O)
{
    __shared__ __align__(16) __half Ks[2][64][72];   // [buf][key][dk]
    __shared__ __align__(16) __half Vs[2][64][72];   // [buf][key][dk]

    const int b = blockIdx.z, h = blockIdx.y;
    const int tid = threadIdx.x, lane = tid & 31, wid = tid >> 5;
    const int gp = lane >> 2, tg = lane & 3;
    const int qrow0 = blockIdx.x * 128 + wid * 16 + gp;

    const __half* Qb = QKV + (size_t)(b * S_) * QKV_S + h * DK_;
    const __half* Kb = Qb + D_;
    const __half* Vb = Qb + 2 * D_;

    const uint32_t ksb = smem_u32(&Ks[0][0][0]);
    const uint32_t vsb = smem_u32(&Vs[0][0][0]);

    int ckey[2], cch[2];
    #pragma unroll
    for (int p = 0; p < 2; p++) {
        const int c = tid + 256 * p;
        ckey[p] = c >> 3; cch[p] = c & 7;
    }
    auto issue_kv = [&](int kt, int buf) {
        const uint32_t kb = ksb + (uint32_t)buf * ATT_BUFB;
        const uint32_t vb = vsb + (uint32_t)buf * ATT_BUFB;
        #pragma unroll
        for (int p = 0; p < 2; p++) {
            const size_t g = (size_t)(kt + ckey[p]) * QKV_S + cch[p] * 8;
            const uint32_t off = (uint32_t)(ckey[p] * ATT_ROWB + cch[p] * 16);
            cp16(kb + off, Kb + g);
            cp16(vb + off, Vb + g);
        }
        cp_commit();
    };

    const uint32_t kcon = (uint32_t)(((((lane >> 4) & 1) * 8 + (lane & 7)) * ATT_ROWB)
                                     + (((lane >> 3) & 1) * 8) * 2);
    const uint32_t vcon = (uint32_t)((((lane >> 3) & 1) * 8 + (lane & 7)) * ATT_ROWB
                                     + (((lane >> 4) & 1) * 8) * 2);

    // Q fragments with 1/8 folded in (fp16 0.125 = 0x3000, exact power of 2)
    uint32_t qf[4][4];
    {
        const __half* q0p = Qb + (size_t)qrow0 * QKV_S;
        const __half* q1p = q0p + (size_t)8 * QKV_S;
        const uint32_t s125 = 0x30003000u;
        #pragma unroll
        for (int s = 0; s < 4; s++) {
            qf[s][0] = *(const uint32_t*)&q0p[16*s + 2*tg];
            qf[s][1] = *(const uint32_t*)&q1p[16*s + 2*tg];
            qf[s][2] = *(const uint32_t*)&q0p[16*s + 2*tg + 8];
            qf[s][3] = *(const uint32_t*)&q1p[16*s + 2*tg + 8];
            #pragma unroll
            for (int e = 0; e < 4; e++)
                asm("mul.rn.f16x2 %0, %0, %1;" : "+r"(qf[s][e]) : "r"(s125));
        }
    }

    float oa[8][4];
    #pragma unroll
    for (int j = 0; j < 8; j++)
        #pragma unroll
        for (int e = 0; e < 4; e++) oa[j][e] = 0.f;
    float m0c = -1e30f, m1c = -1e30f, l0 = 0.f, l1 = 0.f;

    // packed mask word rows for this thread's 2 query rows
    const uint32_t* mb0 = mbits + (size_t)(b * S_ + qrow0) * MW;
    const uint32_t* mb1 = mb0 + (size_t)8 * MW;

    issue_kv(0, 0);

    for (int it = 0; it < S_ / 64; it++) {
        asm volatile("cp.async.wait_group 0;" ::: "memory");
        __syncthreads();
        if (it + 1 < S_ / 64) issue_kv((it + 1) * 64, (it + 1) & 1);

        const uint32_t kbuf = ksb + (uint32_t)(it & 1) * ATT_BUFB;
        const uint32_t vbuf = vsb + (uint32_t)(it & 1) * ATT_BUFB;

        // S = (Q/8)·K^T
        float sc[8][4];
        #pragma unroll
        for (int j = 0; j < 8; j++)
            #pragma unroll
            for (int e = 0; e < 4; e++) sc[j][e] = 0.f;
        #pragma unroll
        for (int s = 0; s < 4; s++) {
            #pragma unroll
            for (int jj = 0; jj < 4; jj++) {
                uint32_t kf[4];
                ldsm4(kf, kbuf + (uint32_t)(jj * 2 * 8 * ATT_ROWB + s * 32) + kcon);
                mma16h(sc[2*jj],     qf[s], kf[0], kf[1]);
                mma16h(sc[2*jj + 1], qf[s], kf[2], kf[3]);
            }
        }

        // mask from packed bits: 2 words per row cover the 64-key tile
        {
            const uint2 bw0 = *(const uint2*)&mb0[it * 2];
            const uint2 bw1 = *(const uint2*)&mb1[it * 2];
            #pragma unroll
            for (int j = 0; j < 8; j++) {
                const uint32_t w0 = (j < 4) ? bw0.x : bw0.y;
                const uint32_t w1 = (j < 4) ? bw1.x : bw1.y;
                const int pos = (j & 3) * 8 + 2 * tg;
                if ((w0 >> pos) & 1)       sc[j][0] = -10000.0f;
                if ((w0 >> (pos + 1)) & 1) sc[j][1] = -10000.0f;
                if ((w1 >> pos) & 1)       sc[j][2] = -10000.0f;
                if ((w1 >> (pos + 1)) & 1) sc[j][3] = -10000.0f;
            }
        }

        // online softmax
        float t0 = -1e30f, t1 = -1e30f;
        #pragma unroll
        for (int j = 0; j < 8; j++) {
            t0 = fmaxf(t0, fmaxf(sc[j][0], sc[j][1]));
            t1 = fmaxf(t1, fmaxf(sc[j][2], sc[j][3]));
        }
        t0 = fmaxf(t0, __shfl_xor_sync(0xffffffffu, t0, 1));
        t0 = fmaxf(t0, __shfl_xor_sync(0xffffffffu, t0, 2));
        t1 = fmaxf(t1, __shfl_xor_sync(0xffffffffu, t1, 1));
        t1 = fmaxf(t1, __shfl_xor_sync(0xffffffffu, t1, 2));
        const float mn0 = fmaxf(m0c, t0), mn1 = fmaxf(m1c, t1);
        const float cr0 = __expf(m0c - mn0), cr1 = __expf(m1c - mn1);
        float ps0 = 0.f, ps1 = 0.f;
        #pragma unroll
        for (int j = 0; j < 8; j++) {
            sc[j][0] = __expf(sc[j][0] - mn0); ps0 += sc[j][0];
            sc[j][1] = __expf(sc[j][1] - mn0); ps0 += sc[j][1];
            sc[j][2] = __expf(sc[j][2] - mn1); ps1 += sc[j][2];
            sc[j][3] = __expf(sc[j][3] - mn1); ps1 += sc[j][3];
        }
        ps0 += __shfl_xor_sync(0xffffffffu, ps0, 1);
        ps0 += __shfl_xor_sync(0xffffffffu, ps0, 2);
        ps1 += __shfl_xor_sync(0xffffffffu, ps1, 1);
        ps1 += __shfl_xor_sync(0xffffffffu, ps1, 2);
        l0 = l0 * cr0 + ps0; m0c = mn0;
        l1 = l1 * cr1 + ps1; m1c = mn1;
        #pragma unroll
        for (int j = 0; j < 8; j++) {
            mul2x(&oa[j][0], cr0);   // packed rescale, bit-identical
            mul2x(&oa[j][2], cr1);
        }

        // P -> fp16 A fragments (layout identity)
        uint32_t pa[4][4];
        #pragma unroll
        for (int t = 0; t < 4; t++) {
            pa[t][0] = f16pk(sc[2*t][0],     sc[2*t][1]);
            pa[t][1] = f16pk(sc[2*t][2],     sc[2*t][3]);
            pa[t][2] = f16pk(sc[2*t + 1][0], sc[2*t + 1][1]);
            pa[t][3] = f16pk(sc[2*t + 1][2], sc[2*t + 1][3]);
        }

        // O += P·V via ldmatrix.trans fragments
        #pragma unroll
        for (int t = 0; t < 4; t++) {
            #pragma unroll
            for (int jj = 0; jj < 4; jj++) {
                uint32_t vf[4];
                ldsm4t(vf, vbuf + (uint32_t)(t * 16 * ATT_ROWB + jj * 2 * 16) + vcon);
                mma16h(oa[2*jj],     pa[t], vf[0], vf[1]);
                mma16h(oa[2*jj + 1], pa[t], vf[2], vf[3]);
            }
        }
    }

    const float inv0 = 1.0f / l0, inv1 = 1.0f / l1;
    __half* o0 = O + ((size_t)(b * S_ + qrow0)) * D_ + h * DK_;
    __half* o1 = o0 + (size_t)8 * D_;
    #pragma unroll
    for (int j = 0; j < 8; j++) {
        *(uint32_t*)&o0[8*j + 2*tg] = f16pk(oa[j][0] * inv0, oa[j][1] * inv0);
        *(uint32_t*)&o1[8*j + 2*tg] = f16pk(oa[j][2] * inv1, oa[j][3] * inv1);
    }
}

// ---------------- launcher ----------------------------------------------------
extern "C" void kernel_launch(void* const* d_in, const int* in_sizes, int n_in,
                              void* d_out, int out_size)
{
    const float* x  = (const float*)d_in[0];
    const int*   mask = (const int*)d_in[1];
    const float* Wq = (const float*)d_in[2];  const float* bq = (const float*)d_in[3];
    const float* Wk = (const float*)d_in[4];  const float* bk = (const float*)d_in[5];
    const float* Wv = (const float*)d_in[6];  const float* bv = (const float*)d_in[7];
    const float* Wo = (const float*)d_in[8];  const float* bo = (const float*)d_in[9];
    const float* W1 = (const float*)d_in[10]; const float* b1 = (const float*)d_in[11];
    const float* W2 = (const float*)d_in[12]; const float* b2 = (const float*)d_in[13];
    const float* ga = (const float*)d_in[14]; const float* ba = (const float*)d_in[15];
    const float* gf = (const float*)d_in[16]; const float* bf = (const float*)d_in[17];
    float* out = (float*)d_out;

    __half *nxh, *qkvh, *ctxh, *nx2h, *hh, *wqkvh, *woh, *w1h, *w2h;
    float *x1, *bqkv;
    uint32_t* mbits;
    cudaGetSymbolAddress((void**)&nxh,   g_nxh);
    cudaGetSymbolAddress((void**)&qkvh,  g_qkvh);
    cudaGetSymbolAddress((void**)&ctxh,  g_ctxh);
    cudaGetSymbolAddress((void**)&x1,    g_x1);
    cudaGetSymbolAddress((void**)&nx2h,  g_nx2h);
    cudaGetSymbolAddress((void**)&hh,    g_hh);
    cudaGetSymbolAddress((void**)&wqkvh, g_wqkvh);
    cudaGetSymbolAddress((void**)&bqkv,  g_bqkv);
    cudaGetSymbolAddress((void**)&woh,   g_woh);
    cudaGetSymbolAddress((void**)&w1h,   g_w1h);
    cudaGetSymbolAddress((void**)&w2h,   g_w2h);
    cudaGetSymbolAddress((void**)&mbits, g_mbits);

    cudaFuncSetAttribute(gemm_f16<EPI_H16>,
                         cudaFuncAttributeMaxDynamicSharedMemorySize, GEMM_SMEM);
    cudaFuncSetAttribute(gemm_f16<EPI_RES>,
                         cudaFuncAttributeMaxDynamicSharedMemorySize, GEMM_SMEM);
    cudaFuncSetAttribute(gemm_f16<EPI_G16>,
                         cudaFuncAttributeMaxDynamicSharedMemorySize, GEMM_SMEM);

    cvt_all_kernel<<<CVT_GRID, 256>>>(Wq, Wk, Wv, Wo, W1, W2, bq, bk, bv,
                                      wqkvh, woh, w1h, w2h, bqkv);
    mask_bits_kernel<<<ROWS * MW / 8, 256>>>(mask, mbits);
    ln_kernel<<<ROWS, 256>>>(x, ga, ba, nxh);

    dim3 gqkv(QKV_S / 128, ROWS / 128);
    gemm_f16<EPI_H16><<<gqkv, 128, GEMM_SMEM>>>(ROWS, QKV_S, D_, nxh, wqkvh,
                                                bqkv, nullptr, qkvh);

    attn_mma<<<dim3(S_ / 128, H_, B_), 256>>>(qkvh, mbits, ctxh);

    dim3 g1(D_ / 128, ROWS / 128);
    gemm_f16<EPI_RES><<<g1, 128, GEMM_SMEM>>>(ROWS, D_, D_, ctxh, woh, bo, x, x1);

    ln_kernel<<<ROWS, 256>>>(x1, gf, bf, nx2h);

    dim3 g2(DFF_ / 128, ROWS / 128);
    gemm_f16<EPI_G16><<<g2, 128, GEMM_SMEM>>>(ROWS, DFF_, D_, nx2h, w1h, b1,
                                              nullptr, hh);

    gemm_f16<EPI_RES><<<g1, 128, GEMM_SMEM>>>(ROWS, D_, DFF_, hh, w2h, b2, x1, out);
}